// round 1
// baseline (speedup 1.0000x reference)
#include <cuda_runtime.h>
#include <cstdint>

// Problem dims
#define BB 64
#define TT 1024
#define HH 256          // = F*F
#define FF 16
#define RR 16
#define NG 4

// ---------------- device scratch (allowed: __device__ globals) ----------------
__device__ float g_Aih[256 * 64];          // [d][o], o = g*16+s
__device__ float g_Ahh[256 * 64];          // [d][o]
__device__ float g_Bc [4 * 32 * 256];      // [g][s2][j]; s2<16: ih, s2>=16: hh
__device__ float g_bias[4 * 256];          // [g][j] = ih_bias + hh_bias
__device__ float g_Z  [BB * TT * 64];      // [n][o], n = b*TT + t, o = g*16+s

// ---------------- helpers ----------------
__device__ __forceinline__ float sigmoid_f(float x) {
    x = fminf(fmaxf(x, -30.f), 30.f);
    return __fdividef(1.f, 1.f + __expf(-x));
}
__device__ __forceinline__ float tanh_f(float x) {
    float xc = fminf(fmaxf(x, -15.f), 15.f);
    float e = __expf(-2.f * xc);
    return __fdividef(1.f - e, 1.f + e);
}

// ---------------- kernel A: compose rank-16 factors ----------------
__global__ void compose_kernel(const float* __restrict__ ih0, const float* __restrict__ ih1,
                               const float* __restrict__ ih2, const float* __restrict__ ih3,
                               const float* __restrict__ ihb,
                               const float* __restrict__ hh0, const float* __restrict__ hh1,
                               const float* __restrict__ hh2, const float* __restrict__ hh3,
                               const float* __restrict__ hhb) {
    int tid = threadIdx.x;
    // A[g][(m,n)][s] = sum_r g0[g,m,r] * g1[g,r,n,s]   (4*256*16 entries)
    for (int idx = tid; idx < 4 * 256 * 16; idx += blockDim.x) {
        int s = idx & 15;
        int d = (idx >> 4) & 255;
        int g = idx >> 12;
        int m = d >> 4, n = d & 15;
        float a_ih = 0.f, a_hh = 0.f;
        #pragma unroll
        for (int r = 0; r < 16; r++) {
            a_ih += ih0[(g * 16 + m) * 16 + r] * ih1[((g * 16 + r) * 16 + n) * 16 + s];
            a_hh += hh0[(g * 16 + m) * 16 + r] * hh1[((g * 16 + r) * 16 + n) * 16 + s];
        }
        g_Aih[d * 64 + g * 16 + s] = a_ih;
        g_Ahh[d * 64 + g * 16 + s] = a_hh;
    }
    // B[g][s][(o,p)] = sum_t g2[g,s,o,t] * g3[g,t,p]   (4*16*256 entries)
    for (int idx = tid; idx < 4 * 16 * 256; idx += blockDim.x) {
        int j = idx & 255;
        int s = (idx >> 8) & 15;
        int g = idx >> 12;
        int o = j >> 4, p = j & 15;
        float b_ih = 0.f, b_hh = 0.f;
        #pragma unroll
        for (int t = 0; t < 16; t++) {
            b_ih += ih2[((g * 16 + s) * 16 + o) * 16 + t] * ih3[(g * 16 + t) * 16 + p];
            b_hh += hh2[((g * 16 + s) * 16 + o) * 16 + t] * hh3[(g * 16 + t) * 16 + p];
        }
        g_Bc[(g * 32 + s) * 256 + j]      = b_ih;   // s2 = s       (ih part)
        g_Bc[(g * 32 + 16 + s) * 256 + j] = b_hh;   // s2 = 16 + s  (hh part)
    }
    for (int idx = tid; idx < 1024; idx += blockDim.x)
        g_bias[idx] = ihb[idx] + hhb[idx];
}

// ---------------- kernel B: Z = X @ A_ih (stage-1 of ih TT-linear) ----------------
__global__ __launch_bounds__(256) void z_kernel(const float* __restrict__ x) {
    __shared__ __align__(16) float xs[256];
    int tid = threadIdx.x;
    int o  = tid >> 2;     // output index 0..63 (= g*16+s)
    int kq = tid & 3;      // k-quarter

    float wa[64];
    #pragma unroll
    for (int i = 0; i < 64; i++) wa[i] = g_Aih[(kq * 64 + i) * 64 + o];

    for (int n = blockIdx.x; n < BB * TT; n += gridDim.x) {
        __syncthreads();
        xs[tid] = x[n * 256 + tid];
        __syncthreads();
        float acc = 0.f;
        const float4* xp = (const float4*)(xs + kq * 64);
        #pragma unroll
        for (int i4 = 0; i4 < 16; i4++) {
            float4 v = xp[i4];
            acc += wa[i4 * 4 + 0] * v.x;
            acc += wa[i4 * 4 + 1] * v.y;
            acc += wa[i4 * 4 + 2] * v.z;
            acc += wa[i4 * 4 + 3] * v.w;
        }
        acc += __shfl_xor_sync(0xffffffffu, acc, 1);
        acc += __shfl_xor_sync(0xffffffffu, acc, 2);
        if (kq == 0) g_Z[n * 64 + o] = acc;
    }
}

// ---------------- kernel C: recurrent scan, one CTA per batch element ----------------
__global__ __launch_bounds__(256, 1) void scan_kernel(float* __restrict__ out, int write_hc) {
    __shared__ __align__(16) float hs[256];      // h_{t-1}
    __shared__ __align__(16) float zc[4][32];    // [g][s2] : s2<16 ih-z, s2>=16 hh-z
    __shared__ __align__(16) float gs[4][256];   // gate pre-activations

    int tid = threadIdx.x;
    int b   = blockIdx.x;

    // stage-1 role: (o, kq)
    int o  = tid >> 2;
    int kq = tid & 3;
    float wa[64];
    #pragma unroll
    for (int i = 0; i < 64; i++) wa[i] = g_Ahh[(kq * 64 + i) * 64 + o];

    // stage-2 role: (gate g2i, j-quad jq)
    int g2i = tid >> 6;
    int jq  = tid & 63;
    float4 wb[32];
    #pragma unroll
    for (int s2 = 0; s2 < 32; s2++)
        wb[s2] = *(const float4*)&g_Bc[(g2i * 32 + s2) * 256 + jq * 4];
    float4 bias4 = *(const float4*)&g_bias[g2i * 256 + jq * 4];

    // state owner role: j = tid
    float c = 0.f;
    hs[tid] = 0.f;

    // prefetch z_ih for t = 0
    float zreg = (tid < 64) ? g_Z[(b * TT + 0) * 64 + tid] : 0.f;
    __syncthreads();

    const float* zbase = g_Z + b * TT * 64;
    float* outb = out + (size_t)b * TT * HH;

    for (int t = 0; t < TT; t++) {
        // deposit prefetched z_ih
        if (tid < 64) zc[tid >> 4][tid & 15] = zreg;

        // stage 1: zh[o] = sum_k Ahh[k][o] * h[k]
        float acc = 0.f;
        const float4* hp = (const float4*)(hs + kq * 64);
        #pragma unroll
        for (int i4 = 0; i4 < 16; i4++) {
            float4 h4 = hp[i4];
            acc += wa[i4 * 4 + 0] * h4.x;
            acc += wa[i4 * 4 + 1] * h4.y;
            acc += wa[i4 * 4 + 2] * h4.z;
            acc += wa[i4 * 4 + 3] * h4.w;
        }
        acc += __shfl_xor_sync(0xffffffffu, acc, 1);
        acc += __shfl_xor_sync(0xffffffffu, acc, 2);
        if (kq == 0) zc[o >> 4][16 + (o & 15)] = acc;

        // prefetch next step's z_ih (latency hidden under stage 2)
        if (t < TT - 1 && tid < 64) zreg = zbase[(t + 1) * 64 + tid];

        __syncthreads();   // zc complete

        // stage 2: gates[g][j0..j0+3] = bias + sum_s2 zc[g][s2] * Bc[g][s2][j]
        float4 a4 = bias4;
        #pragma unroll
        for (int s2 = 0; s2 < 32; s2++) {
            float  zv = zc[g2i][s2];
            float4 w4 = wb[s2];
            a4.x += zv * w4.x;
            a4.y += zv * w4.y;
            a4.z += zv * w4.z;
            a4.w += zv * w4.w;
        }
        *(float4*)&gs[g2i][jq * 4] = a4;

        __syncthreads();   // gates complete

        // LSTM cell update for j = tid
        float gi = gs[0][tid];
        float gf = gs[1][tid];
        float gg = gs[2][tid];
        float go = gs[3][tid];
        float i_ = sigmoid_f(gi);
        float f_ = sigmoid_f(gf);
        float g_ = tanh_f(gg);
        float o_ = sigmoid_f(go);
        c = f_ * c + i_ * g_;
        float h = o_ * tanh_f(c);

        __syncthreads();   // all gate reads done; safe to overwrite hs / zc next iter
        hs[tid] = h;
        outb[t * HH + tid] = h;
        __syncthreads();   // hs ready for next step's stage 1
    }

    if (write_hc) {
        out[(size_t)BB * TT * HH + b * HH + tid]            = hs[tid];  // final h
        out[(size_t)BB * TT * HH + BB * HH + b * HH + tid]  = c;        // final c
    }
}

// ---------------- launch ----------------
extern "C" void kernel_launch(void* const* d_in, const int* in_sizes, int n_in,
                              void* d_out, int out_size) {
    const float* x   = (const float*)d_in[0];
    const float* ih0 = (const float*)d_in[1];
    const float* ih1 = (const float*)d_in[2];
    const float* ih2 = (const float*)d_in[3];
    const float* ih3 = (const float*)d_in[4];
    const float* ihb = (const float*)d_in[5];
    const float* hh0 = (const float*)d_in[6];
    const float* hh1 = (const float*)d_in[7];
    const float* hh2 = (const float*)d_in[8];
    const float* hh3 = (const float*)d_in[9];
    const float* hhb = (const float*)d_in[10];

    compose_kernel<<<1, 256>>>(ih0, ih1, ih2, ih3, ihb, hh0, hh1, hh2, hh3, hhb);
    z_kernel<<<444, 256>>>(x);

    long long need = (long long)BB * TT * HH + 2LL * BB * HH;
    int whc = ((long long)out_size >= need) ? 1 : 0;
    scan_kernel<<<BB, 256>>>((float*)d_out, whc);
}

// round 2
// speedup vs baseline: 1.1493x; 1.1493x over previous
#include <cuda_runtime.h>
#include <cstdint>

#define BB 64
#define TT 1024
#define HH 256
#define NG 4

typedef unsigned long long ull;

// ---------------- device scratch ----------------
__device__ float g_Aih[256 * 64];          // [d][o], o = g*16+s
__device__ float g_Ahh[256 * 64];          // [d][o]
__device__ float g_Bc [4 * 32 * 256];      // [g][s2][j]; s2<16: ih, s2>=16: hh
__device__ float g_bias[4 * 256];          // [g][j]
__device__ float g_Z  [BB * TT * 64];      // [n][o]

// ---------------- packed f32x2 helpers ----------------
__device__ __forceinline__ ull ffma2(ull a, ull b, ull c) {
    ull d;
    asm("fma.rn.f32x2 %0, %1, %2, %3;" : "=l"(d) : "l"(a), "l"(b), "l"(c));
    return d;
}
__device__ __forceinline__ ull pack2(float lo, float hi) {
    ull r; asm("mov.b64 %0, {%1,%2};" : "=l"(r) : "f"(lo), "f"(hi)); return r;
}
__device__ __forceinline__ float hsum2(ull v) {
    float lo, hi; asm("mov.b64 {%0,%1}, %2;" : "=f"(lo), "=f"(hi) : "l"(v));
    return lo + hi;
}

__device__ __forceinline__ float sigmoid_f(float x) {
    x = fminf(fmaxf(x, -30.f), 30.f);
    return __fdividef(1.f, 1.f + __expf(-x));
}
__device__ __forceinline__ float tanh_f(float x) {
    float xc = fminf(fmaxf(x, -15.f), 15.f);
    float e = __expf(-2.f * xc);
    return __fdividef(1.f - e, 1.f + e);
}

// ---------------- kernel A: compose rank-16 factors (parallel) ----------------
__global__ void compose_kernel(const float* __restrict__ ih0, const float* __restrict__ ih1,
                               const float* __restrict__ ih2, const float* __restrict__ ih3,
                               const float* __restrict__ ihb,
                               const float* __restrict__ hh0, const float* __restrict__ hh1,
                               const float* __restrict__ hh2, const float* __restrict__ hh3,
                               const float* __restrict__ hhb) {
    int tid = blockIdx.x * blockDim.x + threadIdx.x;
    int stride = gridDim.x * blockDim.x;
    // A[g][(m,n)][s] = sum_r g0[g,m,r] * g1[g,r,n,s]
    for (int idx = tid; idx < 4 * 256 * 16; idx += stride) {
        int s = idx & 15;
        int d = (idx >> 4) & 255;
        int g = idx >> 12;
        int m = d >> 4, n = d & 15;
        float a_ih = 0.f, a_hh = 0.f;
        #pragma unroll
        for (int r = 0; r < 16; r++) {
            a_ih += ih0[(g * 16 + m) * 16 + r] * ih1[((g * 16 + r) * 16 + n) * 16 + s];
            a_hh += hh0[(g * 16 + m) * 16 + r] * hh1[((g * 16 + r) * 16 + n) * 16 + s];
        }
        g_Aih[d * 64 + g * 16 + s] = a_ih;
        g_Ahh[d * 64 + g * 16 + s] = a_hh;
    }
    // B[g][s][(o,p)] = sum_t g2[g,s,o,t] * g3[g,t,p]
    for (int idx = tid; idx < 4 * 16 * 256; idx += stride) {
        int j = idx & 255;
        int s = (idx >> 8) & 15;
        int g = idx >> 12;
        int o = j >> 4, p = j & 15;
        float b_ih = 0.f, b_hh = 0.f;
        #pragma unroll
        for (int t = 0; t < 16; t++) {
            b_ih += ih2[((g * 16 + s) * 16 + o) * 16 + t] * ih3[(g * 16 + t) * 16 + p];
            b_hh += hh2[((g * 16 + s) * 16 + o) * 16 + t] * hh3[(g * 16 + t) * 16 + p];
        }
        g_Bc[(g * 32 + s) * 256 + j]      = b_ih;
        g_Bc[(g * 32 + 16 + s) * 256 + j] = b_hh;
    }
    for (int idx = tid; idx < 1024; idx += stride)
        g_bias[idx] = ihb[idx] + hhb[idx];
}

// ---------------- kernel B: Z = X @ A_ih ----------------
__global__ __launch_bounds__(256) void z_kernel(const float* __restrict__ x) {
    __shared__ __align__(16) float xs[256];
    int tid = threadIdx.x;
    int o  = tid >> 2;     // 0..63
    int kq = tid & 3;

    ull wa2[32];
    #pragma unroll
    for (int i = 0; i < 32; i++)
        wa2[i] = pack2(g_Aih[(kq * 64 + 2 * i) * 64 + o],
                       g_Aih[(kq * 64 + 2 * i + 1) * 64 + o]);

    for (int n = blockIdx.x; n < BB * TT; n += gridDim.x) {
        __syncthreads();
        xs[tid] = x[n * 256 + tid];
        __syncthreads();
        const ulonglong2* hp = (const ulonglong2*)(xs + kq * 64);
        ull acc_a = 0ULL, acc_b = 0ULL;
        #pragma unroll
        for (int i2 = 0; i2 < 16; i2++) {
            ulonglong2 v = hp[i2];
            acc_a = ffma2(wa2[2 * i2],     v.x, acc_a);
            acc_b = ffma2(wa2[2 * i2 + 1], v.y, acc_b);
        }
        float acc = hsum2(acc_a) + hsum2(acc_b);
        acc += __shfl_xor_sync(0xffffffffu, acc, 1);
        acc += __shfl_xor_sync(0xffffffffu, acc, 2);
        if (kq == 0) g_Z[n * 64 + o] = acc;
    }
}

// ---------------- kernel C: recurrent scan, one CTA per batch ----------------
__global__ __launch_bounds__(256, 1) void scan_kernel(float* __restrict__ out, int write_hc) {
    __shared__ __align__(16) float hs[256];      // h_{t-1}
    __shared__ __align__(16) float zc[4][32];    // [g][s2]: s2<16 ih, s2>=16 hh

    int tid = threadIdx.x;
    int b   = blockIdx.x;

    // stage-1 role: (o, kq) — zh[o] = sum_k Ahh[k][o] h[k]
    int o  = tid >> 2;
    int kq = tid & 3;
    ull wa2[32];
    #pragma unroll
    for (int i = 0; i < 32; i++)
        wa2[i] = pack2(g_Ahh[(kq * 64 + 2 * i) * 64 + o],
                       g_Ahh[(kq * 64 + 2 * i + 1) * 64 + o]);

    // stage-2 role: thread owns column j = tid, all 4 gates
    int j = tid;
    ull wb2[64];                    // [g*16 + p], pair over s2
    #pragma unroll
    for (int g = 0; g < 4; g++)
        #pragma unroll
        for (int p = 0; p < 16; p++)
            wb2[g * 16 + p] = pack2(g_Bc[(g * 32 + 2 * p) * 256 + j],
                                    g_Bc[(g * 32 + 2 * p + 1) * 256 + j]);
    float bias_r[4];
    #pragma unroll
    for (int g = 0; g < 4; g++) bias_r[g] = g_bias[g * 256 + j];

    float c = 0.f;
    hs[tid] = 0.f;
    float zreg = (tid < 64) ? g_Z[(b * TT) * 64 + tid] : 0.f;
    __syncthreads();

    const float* zbase = g_Z + (size_t)b * TT * 64;
    float* outb = out + (size_t)b * TT * HH;

    for (int t = 0; t < TT; t++) {
        // deposit prefetched z_ih
        if (tid < 64) zc[tid >> 4][tid & 15] = zreg;

        // stage 1: packed-FMA partial dot over 64 h entries
        {
            const ulonglong2* hp = (const ulonglong2*)(hs + kq * 64);
            ull acc_a = 0ULL, acc_b = 0ULL;
            #pragma unroll
            for (int i2 = 0; i2 < 16; i2++) {
                ulonglong2 v = hp[i2];
                acc_a = ffma2(wa2[2 * i2],     v.x, acc_a);
                acc_b = ffma2(wa2[2 * i2 + 1], v.y, acc_b);
            }
            float acc = hsum2(acc_a) + hsum2(acc_b);
            acc += __shfl_xor_sync(0xffffffffu, acc, 1);
            acc += __shfl_xor_sync(0xffffffffu, acc, 2);
            if (kq == 0) zc[o >> 4][16 + (o & 15)] = acc;
        }
        __syncthreads();   // sync1: zc complete

        // prefetch next z_ih (hidden under stage 2)
        if (t < TT - 1 && tid < 64) zreg = zbase[(t + 1) * 64 + tid];

        // stage 2 + gate math, fully register-resident
        float gate[4];
        #pragma unroll
        for (int g = 0; g < 4; g++) {
            const ulonglong2* zp = (const ulonglong2*)(zc[g]);
            ull acc = 0ULL;
            #pragma unroll
            for (int q = 0; q < 8; q++) {
                ulonglong2 v = zp[q];
                acc = ffma2(wb2[g * 16 + 2 * q],     v.x, acc);
                acc = ffma2(wb2[g * 16 + 2 * q + 1], v.y, acc);
            }
            gate[g] = hsum2(acc) + bias_r[g];
        }

        float i_ = sigmoid_f(gate[0]);
        float f_ = sigmoid_f(gate[1]);
        float g_ = tanh_f(gate[2]);
        float o_ = sigmoid_f(gate[3]);
        c = f_ * c + i_ * g_;
        float h = o_ * tanh_f(c);

        // safe: all stage-1 reads of hs happened before sync1
        hs[tid] = h;
        outb[t * HH + tid] = h;
        __syncthreads();   // sync2: hs ready, zc consumable next iter
    }

    if (write_hc) {
        out[(size_t)BB * TT * HH + b * HH + tid]           = hs[tid];
        out[(size_t)BB * TT * HH + BB * HH + b * HH + tid] = c;
    }
}

// ---------------- launch ----------------
extern "C" void kernel_launch(void* const* d_in, const int* in_sizes, int n_in,
                              void* d_out, int out_size) {
    const float* x   = (const float*)d_in[0];
    const float* ih0 = (const float*)d_in[1];
    const float* ih1 = (const float*)d_in[2];
    const float* ih2 = (const float*)d_in[3];
    const float* ih3 = (const float*)d_in[4];
    const float* ihb = (const float*)d_in[5];
    const float* hh0 = (const float*)d_in[6];
    const float* hh1 = (const float*)d_in[7];
    const float* hh2 = (const float*)d_in[8];
    const float* hh3 = (const float*)d_in[9];
    const float* hhb = (const float*)d_in[10];

    compose_kernel<<<64, 256>>>(ih0, ih1, ih2, ih3, ihb, hh0, hh1, hh2, hh3, hhb);
    z_kernel<<<592, 256>>>(x);

    long long need = (long long)BB * TT * HH + 2LL * BB * HH;
    int whc = ((long long)out_size >= need) ? 1 : 0;
    scan_kernel<<<BB, 256>>>((float*)d_out, whc);
}